// round 7
// baseline (speedup 1.0000x reference)
#include <cuda_runtime.h>

typedef unsigned long long ull;

#define TT 1024
#define BB 64
#define WW 512
#define W3 1536
#define LL 2

#define GRID 128
#define NTH  384             // 12 warps: 0-3 input half (K=128), 4-11 hidden half (K=64)
#define WS   1028            // weight smem row stride (16B-aligned, conflict-free)
#define PS   49              // partials stride (gcd(49,32)=1 -> conflict-free)

#define SM_RM   (24*WS)      // 24672
#define SM_BIA  (SM_RM + BB)
#define SM_BHN  (SM_BIA + 24)
#define SM_PART (SM_BHN + 8) // 24768
#define SM_TOT  (SM_PART + NTH*PS)
#define SMEM_BYTES (SM_TOT*4)

__device__ __align__(256) float g_insT[TT][WW][BB]; // ins transposed [t][k][b]
__device__ __align__(256) float g_h0T[2][WW][BB];   // layer-0 hidden [w][b]
__device__ __align__(256) float g_h1T[2][WW][BB];   // layer-1 hidden [w][b]
__device__ unsigned g_cnt = 0;
__device__ volatile unsigned g_gen = 0;
__device__ int g_reset_mode = 0;

__global__ void sniff_resets_kernel(const unsigned* __restrict__ r)
{
    __shared__ unsigned red[256];
    unsigned m = 0;
    for (int i = threadIdx.x; i < (TT * BB) / 4; i += 256) m = max(m, r[i]);
    red[threadIdx.x] = m;
    __syncthreads();
    for (int s = 128; s > 0; s >>= 1) {
        if (threadIdx.x < s) red[threadIdx.x] = max(red[threadIdx.x], red[threadIdx.x + s]);
        __syncthreads();
    }
    if (threadIdx.x == 0) {
        unsigned mx = red[0];
        g_reset_mode = (mx <= 1u) ? 1 : (mx >= 0x10000000u ? 2 : 0);
    }
}

__device__ __forceinline__ float reset_mask(const void* r, int mode, int idx)
{
    if (mode == 1) return ((const int*)r)[idx] != 0 ? 0.0f : 1.0f;
    if (mode == 2) return ((const float*)r)[idx] != 0.0f ? 0.0f : 1.0f;
    return ((const unsigned char*)r)[idx] != 0 ? 0.0f : 1.0f;
}

// transpose ins: [t][b][w] -> [t][w][b]
__global__ void transpose_ins_kernel(const float* __restrict__ ins)
{
    __shared__ float tile[64][65];
    const int t  = blockIdx.x >> 3;
    const int w0 = (blockIdx.x & 7) * 64;
    const float* src = ins + (size_t)t * BB * WW;
    for (int i = threadIdx.x; i < 64 * 64; i += 256) {
        int b = i >> 6, w = i & 63;
        tile[b][w] = src[b * WW + w0 + w];
    }
    __syncthreads();
    float* dst = &g_insT[t][w0][0];
    for (int i = threadIdx.x; i < 64 * 64; i += 256) {
        int w = i >> 6, b = i & 63;
        dst[w * BB + b] = tile[b][w];
    }
}

__device__ __forceinline__ void ffma2(ull& acc, ull a, ull b)
{ asm("fma.rn.f32x2 %0, %1, %2, %0;" : "+l"(acc) : "l"(a), "l"(b)); }
__device__ __forceinline__ ull dup2(float s)
{ ull r; asm("mov.b64 %0, {%1, %1};" : "=l"(r) : "f"(s)); return r; }
__device__ __forceinline__ float lo2(ull v) { return __uint_as_float((unsigned)v); }
__device__ __forceinline__ float hi2(ull v) { return __uint_as_float((unsigned)(v >> 32)); }
__device__ __forceinline__ float4 ldcg4(const float* p) { return __ldcg((const float4*)p); }

__global__ void __launch_bounds__(NTH, 1)
gru_scan_kernel(const void* __restrict__ resets,
                const float* __restrict__ Wi, const float* __restrict__ bi,
                const float* __restrict__ Wh, const float* __restrict__ bhn,
                float* __restrict__ out)
{
    extern __shared__ float smem[];
    float* Wsm  = smem;              // [24][WS]   weights, [col][k]
    float* rm   = smem + SM_RM;      // [64]
    float* bia  = smem + SM_BIA;     // [24]
    float* bhna = smem + SM_BHN;     // [8]
    float* part = smem + SM_PART;    // [384][PS]

    const int tid  = threadIdx.x;
    const int lane = tid & 31;
    const int warp = tid >> 5;           // 0..11
    const int cta  = blockIdx.x;
    const int group = cta >> 6;          // 0: layer-1 task, 1: layer-0 task
    const int lyr  = group ? 0 : 1;
    const int gwBase = (cta & 63) * 8;   // 8 gate-triples per CTA
    const int rg = lane >> 2;            // batch row-group: rows rg*8..+7
    const int cg = lane & 3;             // col-group: cols cg*6..+5
    const bool ihalf = (warp < 4);       // input half vs hidden half
    const int kbA  = ihalf ? warp * 128 : (warp - 4) * 64;  // k base in src
    const int koff = ihalf ? kbA : 512 + kbA;               // k base in Wsm
    const int nst  = ihalf ? 32 : 16;                       // steps of 4 k
    const int rmode = g_reset_mode;

    // ---- one-time weights/biases to smem ----
    const float* WiL = Wi + (size_t)lyr * WW * W3;
    const float* WhL = Wh + (size_t)lyr * WW * W3;
    for (int idx = tid; idx < 24 * 1024; idx += NTH) {
        int c = idx % 24, k = idx / 24;
        int ttl = c / 3, g = c - ttl * 3;
        int gc = gwBase + ttl + g * WW;
        Wsm[c * WS + k] = (k < WW) ? WiL[(size_t)k * W3 + gc]
                                   : WhL[(size_t)(k - WW) * W3 + gc];
    }
    if (tid < 24) { int ttl = tid / 3, g = tid - ttl * 3;
                    bia[tid] = bi[lyr * W3 + g * WW + gwBase + ttl]; }
    if (tid < 8)  bhna[tid] = bhn[lyr * WW + gwBase + tid];

    unsigned gen = 0;
    if (tid == 0) gen = g_gen;
    __syncthreads();

    float* out_carry = out;
    float* out_ys    = out + LL * BB * WW;
    const float* wB = Wsm + (cg * 6) * WS + koff;

    for (int p = 0; p <= TT; ++p) {
        const bool active = group ? (p < TT) : (p >= 1);
        const int t = group ? p : (p - 1);
        const float* srcH = group ? &g_h0T[(p == 0) ? 1 : ((p - 1) & 1)][0][0]
                                  : &g_h1T[(p == 1) ? 1 : ((p - 1) & 1)][0][0];
        if (active) {
            const bool zeroH = group ? (p == 0) : (p == 1);
            const float* srcI = group ? &g_insT[t][0][0] : &g_h0T[(p - 1) & 1][0][0];

            if (tid < BB)
                rm[tid] = zeroH ? 0.0f : reset_mask(resets, rmode, t * BB + tid);

            // one CTA prefetches the next timestep's ins slab (128 KB) into L2
            if (cta == 64 && p + 1 < TT) {
                const char* nb = (const char*)&g_insT[p + 1][0][0];
#pragma unroll
                for (int q = 0; q < 2; ++q)
                    asm volatile("prefetch.global.L2 [%0];"
                                 :: "l"(nb + (tid * 2 + q) * 128));
            }

            const float* srcA = ihalf ? srcI : srcH;
            const float* aB = srcA + kbA * BB + rg * 8;

            ull acc[4][6];
#pragma unroll
            for (int i = 0; i < 4; ++i)
#pragma unroll
                for (int j = 0; j < 6; ++j) acc[i][j] = 0ull;

#pragma unroll 2
            for (int st = 0; st < nst; ++st) {
                float4 a[8], wv[6];
#pragma unroll
                for (int x = 0; x < 8; ++x)
                    a[x] = ldcg4(aB + (st * 4 + (x >> 1)) * BB + (x & 1) * 4);
#pragma unroll
                for (int j = 0; j < 6; ++j)
                    wv[j] = *(const float4*)(wB + j * WS + st * 4);
#pragma unroll
                for (int kk = 0; kk < 4; ++kk) {
                    const ull* ap = (const ull*)&a[kk * 2];   // 4 batch-pair ulls
#pragma unroll
                    for (int j = 0; j < 6; ++j) {
                        ull w2 = dup2(((const float*)&wv[j])[kk]);
                        ffma2(acc[0][j], ap[0], w2);
                        ffma2(acc[1][j], ap[1], w2);
                        ffma2(acc[2][j], ap[2], w2);
                        ffma2(acc[3][j], ap[3], w2);
                    }
                }
            }

            // publish partials (stride 49 -> conflict-free)
            float* mp = part + tid * PS;
#pragma unroll
            for (int ip = 0; ip < 4; ++ip)
#pragma unroll
                for (int j = 0; j < 6; ++j) {
                    mp[(2 * ip) * 6 + j]     = lo2(acc[ip][j]);
                    mp[(2 * ip + 1) * 6 + j] = hi2(acc[ip][j]);
                }
        }

        __syncthreads();

        if (active) {
#pragma unroll
            for (int e = 0; e < 2; ++e) {
                const int idx = tid + e * NTH;          // 0..511 (second pass tid<128)
                if (idx < 512) {
                    const int b = idx >> 3, ttl = idx & 7;
                    const float m = rm[b];
                    const int lpos = (b >> 3) * 4;      // lane row-group base
                    const int roff = (b & 7) * 6;
                    float si[3], sh[3];
#pragma unroll
                    for (int g = 0; g < 3; ++g) {
                        const int c = ttl * 3 + g;
                        const float* pp = part + (lpos + c / 6) * PS + roff + c % 6;
                        si[g] = pp[0 * 32 * PS] + pp[1 * 32 * PS]
                              + pp[2 * 32 * PS] + pp[3 * 32 * PS];
                        sh[g] = pp[4 * 32 * PS] + pp[5 * 32 * PS]
                              + pp[6 * 32 * PS] + pp[7 * 32 * PS]
                              + pp[8 * 32 * PS] + pp[9 * 32 * PS]
                              + pp[10 * 32 * PS] + pp[11 * 32 * PS];
                    }
                    const float r = 1.0f / (1.0f + __expf(-(bia[ttl * 3 + 0] + si[0] + m * sh[0])));
                    const float z = 1.0f / (1.0f + __expf(-(bia[ttl * 3 + 1] + si[1] + m * sh[1])));
                    const float n = tanhf(bia[ttl * 3 + 2] + si[2] + r * (m * sh[2] + bhna[ttl]));
                    const int w = gwBase + ttl;
                    const float hp = m * __ldcg(srcH + w * BB + b);
                    const float h = (1.0f - z) * n + z * hp;

                    float* dstT = group ? &g_h0T[p & 1][0][0] : &g_h1T[p & 1][0][0];
                    dstT[w * BB + b] = h;
                    if (group == 0) {
                        out_ys[(size_t)t * BB * WW + b * WW + w] = h;
                        if (p == TT) out_carry[BB * WW + b * WW + w] = h;
                    } else if (p == TT - 1) {
                        out_carry[b * WW + w] = h;
                    }
                }
            }
        }

        // grid barrier
        __syncthreads();
        if (tid == 0) {
            __threadfence();
            unsigned a = atomicAdd(&g_cnt, 1);
            gen += 1;
            if (a == GRID - 1) {
                g_cnt = 0;
                __threadfence();
                g_gen = gen;
            } else {
                while (g_gen < gen) { __nanosleep(20); }
                __threadfence();
            }
        }
        __syncthreads();
    }
}

extern "C" void kernel_launch(void* const* d_in, const int* in_sizes, int n_in,
                              void* d_out, int out_size)
{
    const float* ins    = (const float*)d_in[0];
    const void*  resets = (const void*)d_in[1];
    const float* Wi     = (const float*)d_in[2];
    const float* bi     = (const float*)d_in[3];
    const float* Wh     = (const float*)d_in[4];
    const float* bhn    = (const float*)d_in[5];
    float*       out    = (float*)d_out;

    sniff_resets_kernel<<<1, 256>>>((const unsigned*)resets);
    transpose_ins_kernel<<<TT * 8, 256>>>(ins);

    cudaFuncSetAttribute(gru_scan_kernel,
                         cudaFuncAttributeMaxDynamicSharedMemorySize, SMEM_BYTES);
    gru_scan_kernel<<<GRID, NTH, SMEM_BYTES>>>(resets, Wi, bi, Wh, bhn, out);
}

// round 8
// speedup vs baseline: 1.7182x; 1.7182x over previous
#include <cuda_runtime.h>

typedef unsigned long long ull;

#define TT 1024
#define BB 64
#define WW 512
#define W3 1536
#define LL 2

#define GRID 128
#define NTH  512             // 16 warps: 0-7 input half, 8-15 hidden half, K=64 each
#define WS   1028            // weight smem row stride (16B-aligned, conflict-free)
#define PS   49              // partials stride (gcd(49,32)=1 -> conflict-free)

#define SM_RM   (24*WS)      // 24672
#define SM_BIA  (SM_RM + BB)
#define SM_BHN  (SM_BIA + 24)
#define SM_PART (SM_BHN + 8) // 24768
#define SM_TOT  (SM_PART + NTH*PS)
#define SMEM_BYTES (SM_TOT*4)   // ~195 KB

__device__ __align__(256) float g_insT[TT][WW][BB]; // ins transposed [t][k][b]
__device__ __align__(256) float g_h0T[2][WW][BB];   // layer-0 hidden [w][b]
__device__ __align__(256) float g_h1T[2][WW][BB];   // layer-1 hidden [w][b]
__device__ unsigned g_cnt = 0;
__device__ volatile unsigned g_gen = 0;
__device__ int g_reset_mode = 0;

__global__ void sniff_resets_kernel(const unsigned* __restrict__ r)
{
    __shared__ unsigned red[256];
    unsigned m = 0;
    for (int i = threadIdx.x; i < (TT * BB) / 4; i += 256) m = max(m, r[i]);
    red[threadIdx.x] = m;
    __syncthreads();
    for (int s = 128; s > 0; s >>= 1) {
        if (threadIdx.x < s) red[threadIdx.x] = max(red[threadIdx.x], red[threadIdx.x + s]);
        __syncthreads();
    }
    if (threadIdx.x == 0) {
        unsigned mx = red[0];
        g_reset_mode = (mx <= 1u) ? 1 : (mx >= 0x10000000u ? 2 : 0);
    }
}

__device__ __forceinline__ float reset_mask(const void* r, int mode, int idx)
{
    if (mode == 1) return ((const int*)r)[idx] != 0 ? 0.0f : 1.0f;
    if (mode == 2) return ((const float*)r)[idx] != 0.0f ? 0.0f : 1.0f;
    return ((const unsigned char*)r)[idx] != 0 ? 0.0f : 1.0f;
}

// transpose ins: [t][b][w] -> [t][w][b]
__global__ void transpose_ins_kernel(const float* __restrict__ ins)
{
    __shared__ float tile[64][65];
    const int t  = blockIdx.x >> 3;
    const int w0 = (blockIdx.x & 7) * 64;
    const float* src = ins + (size_t)t * BB * WW;
    for (int i = threadIdx.x; i < 64 * 64; i += 256) {
        int b = i >> 6, w = i & 63;
        tile[b][w] = src[b * WW + w0 + w];
    }
    __syncthreads();
    float* dst = &g_insT[t][w0][0];
    for (int i = threadIdx.x; i < 64 * 64; i += 256) {
        int w = i >> 6, b = i & 63;
        dst[w * BB + b] = tile[b][w];
    }
}

__device__ __forceinline__ void ffma2(ull& acc, ull a, ull b)
{ asm("fma.rn.f32x2 %0, %1, %2, %0;" : "+l"(acc) : "l"(a), "l"(b)); }
__device__ __forceinline__ ull dup2(float s)
{ ull r; asm("mov.b64 %0, {%1, %1};" : "=l"(r) : "f"(s)); return r; }
__device__ __forceinline__ float lo2(ull v) { return __uint_as_float((unsigned)v); }
__device__ __forceinline__ float hi2(ull v) { return __uint_as_float((unsigned)(v >> 32)); }
__device__ __forceinline__ float4 ldcg4(const float* p) { return __ldcg((const float4*)p); }

__global__ void __launch_bounds__(NTH, 1)
gru_scan_kernel(const void* __restrict__ resets,
                const float* __restrict__ Wi, const float* __restrict__ bi,
                const float* __restrict__ Wh, const float* __restrict__ bhn,
                float* __restrict__ out)
{
    extern __shared__ float smem[];
    float* Wsm  = smem;              // [24][WS]   weights, [col][k]
    float* rm   = smem + SM_RM;      // [64]
    float* bia  = smem + SM_BIA;     // [24]
    float* bhna = smem + SM_BHN;     // [8]
    float* part = smem + SM_PART;    // [512][PS]

    const int tid  = threadIdx.x;
    const int lane = tid & 31;
    const int warp = tid >> 5;           // 0..15
    const int cta  = blockIdx.x;
    const int group = cta >> 6;          // 0: layer-1 task, 1: layer-0 task
    const int lyr  = group ? 0 : 1;
    const int gwBase = (cta & 63) * 8;   // 8 gate-triples per CTA
    const int rg = lane >> 2;            // batch row-group: rows rg*8..+7
    const int cg = lane & 3;             // col-group: cols cg*6..+5
    const bool ihalf = (warp < 8);       // input half vs hidden half
    const int kbA  = (warp & 7) * 64;    // k base within the half (K=64 per warp)
    const int koff = ihalf ? kbA : 512 + kbA;  // k base within Wsm
    const int rmode = g_reset_mode;

    // ---- one-time weights/biases to smem ----
    const float* WiL = Wi + (size_t)lyr * WW * W3;
    const float* WhL = Wh + (size_t)lyr * WW * W3;
    for (int idx = tid; idx < 24 * 1024; idx += NTH) {
        int c = idx % 24, k = idx / 24;
        int ttl = c / 3, g = c - ttl * 3;
        int gc = gwBase + ttl + g * WW;
        Wsm[c * WS + k] = (k < WW) ? WiL[(size_t)k * W3 + gc]
                                   : WhL[(size_t)(k - WW) * W3 + gc];
    }
    if (tid < 24) { int ttl = tid / 3, g = tid - ttl * 3;
                    bia[tid] = bi[lyr * W3 + g * WW + gwBase + ttl]; }
    if (tid < 8)  bhna[tid] = bhn[lyr * WW + gwBase + tid];

    unsigned gen = 0;
    if (tid == 0) gen = g_gen;
    __syncthreads();

    float* out_carry = out;
    float* out_ys    = out + LL * BB * WW;
    const float* wB = Wsm + (cg * 6) * WS + koff;

    for (int p = 0; p <= TT; ++p) {
        const bool active = group ? (p < TT) : (p >= 1);
        const int t = group ? p : (p - 1);
        const float* srcH = group ? &g_h0T[(p == 0) ? 1 : ((p - 1) & 1)][0][0]
                                  : &g_h1T[(p == 1) ? 1 : ((p - 1) & 1)][0][0];
        if (active) {
            const bool zeroH = group ? (p == 0) : (p == 1);
            const float* srcI = group ? &g_insT[t][0][0] : &g_h0T[(p - 1) & 1][0][0];

            if (tid < BB)
                rm[tid] = zeroH ? 0.0f : reset_mask(resets, rmode, t * BB + tid);

            // one CTA prefetches the next timestep's ins slab (128 KB) into L2
            if (cta == 64 && p + 1 < TT) {
                const char* nb = (const char*)&g_insT[p + 1][0][0];
                asm volatile("prefetch.global.L2 [%0];" :: "l"(nb + tid * 256));
                asm volatile("prefetch.global.L2 [%0];" :: "l"(nb + tid * 256 + 128));
            }

            const float* srcA = ihalf ? srcI : srcH;
            const float* aB = srcA + kbA * BB + rg * 8;

            ull acc[4][6];
#pragma unroll
            for (int i = 0; i < 4; ++i)
#pragma unroll
                for (int j = 0; j < 6; ++j) acc[i][j] = 0ull;

#pragma unroll 4
            for (int st = 0; st < 32; ++st) {      // 32 steps x 2 k = K 64
                float4 a[4];
#pragma unroll
                for (int x = 0; x < 4; ++x)
                    a[x] = ldcg4(aB + (st * 2 + (x >> 1)) * BB + (x & 1) * 4);
                float2 wv[6];
#pragma unroll
                for (int j = 0; j < 6; ++j)
                    wv[j] = *(const float2*)(wB + j * WS + st * 2);
#pragma unroll
                for (int kk = 0; kk < 2; ++kk) {
                    const ull* ap = (const ull*)&a[kk * 2];   // 4 batch-pair ulls
#pragma unroll
                    for (int j = 0; j < 6; ++j) {
                        ull w2 = dup2(kk ? wv[j].y : wv[j].x);
                        ffma2(acc[0][j], ap[0], w2);
                        ffma2(acc[1][j], ap[1], w2);
                        ffma2(acc[2][j], ap[2], w2);
                        ffma2(acc[3][j], ap[3], w2);
                    }
                }
            }

            // publish partials (stride 49 -> conflict-free)
            float* mp = part + tid * PS;
#pragma unroll
            for (int ip = 0; ip < 4; ++ip)
#pragma unroll
                for (int j = 0; j < 6; ++j) {
                    mp[(2 * ip) * 6 + j]     = lo2(acc[ip][j]);
                    mp[(2 * ip + 1) * 6 + j] = hi2(acc[ip][j]);
                }
        }

        __syncthreads();

        if (active) {
            // epilogue: 512 outputs over 512 threads, 1 each
            const int b = tid >> 3, ttl = tid & 7;
            const float m = rm[b];
            const int lpos = (b >> 3) * 4;      // lane row-group base within warp
            const int roff = (b & 7) * 6;
            float si[3], sh[3];
#pragma unroll
            for (int g = 0; g < 3; ++g) {
                const int c = ttl * 3 + g;
                const float* pp = part + (lpos + c / 6) * PS + roff + c % 6;
                float s0 = 0.0f, s1 = 0.0f;
#pragma unroll
                for (int wv_ = 0; wv_ < 8; ++wv_) {
                    s0 += pp[wv_ * 32 * PS];
                    s1 += pp[(wv_ + 8) * 32 * PS];
                }
                si[g] = s0; sh[g] = s1;
            }
            const float r = 1.0f / (1.0f + __expf(-(bia[ttl * 3 + 0] + si[0] + m * sh[0])));
            const float z = 1.0f / (1.0f + __expf(-(bia[ttl * 3 + 1] + si[1] + m * sh[1])));
            const float n = tanhf(bia[ttl * 3 + 2] + si[2] + r * (m * sh[2] + bhna[ttl]));
            const int w = gwBase + ttl;
            const float hp = m * __ldcg(srcH + w * BB + b);
            const float h = (1.0f - z) * n + z * hp;

            float* dstT = group ? &g_h0T[p & 1][0][0] : &g_h1T[p & 1][0][0];
            dstT[w * BB + b] = h;
            if (group == 0) {
                out_ys[(size_t)t * BB * WW + b * WW + w] = h;
                if (p == TT) out_carry[BB * WW + b * WW + w] = h;
            } else if (p == TT - 1) {
                out_carry[b * WW + w] = h;
            }
        }

        // grid barrier
        __syncthreads();
        if (tid == 0) {
            __threadfence();
            unsigned a = atomicAdd(&g_cnt, 1);
            gen += 1;
            if (a == GRID - 1) {
                g_cnt = 0;
                __threadfence();
                g_gen = gen;
            } else {
                while (g_gen < gen) { __nanosleep(20); }
                __threadfence();
            }
        }
        __syncthreads();
    }
}

extern "C" void kernel_launch(void* const* d_in, const int* in_sizes, int n_in,
                              void* d_out, int out_size)
{
    const float* ins    = (const float*)d_in[0];
    const void*  resets = (const void*)d_in[1];
    const float* Wi     = (const float*)d_in[2];
    const float* bi     = (const float*)d_in[3];
    const float* Wh     = (const float*)d_in[4];
    const float* bhn    = (const float*)d_in[5];
    float*       out    = (float*)d_out;

    sniff_resets_kernel<<<1, 256>>>((const unsigned*)resets);
    transpose_ins_kernel<<<TT * 8, 256>>>(ins);

    cudaFuncSetAttribute(gru_scan_kernel,
                         cudaFuncAttributeMaxDynamicSharedMemorySize, SMEM_BYTES);
    gru_scan_kernel<<<GRID, NTH, SMEM_BYTES>>>(resets, Wi, bi, Wh, bhn, out);
}